// round 14
// baseline (speedup 1.0000x reference)
#include <cuda_runtime.h>
#include <cuda_fp16.h>
#include <cstdint>
#include <math.h>

#define DI __device__ __forceinline__

// ----------------------------------------------------------------------------
// Device scratch (no cudaMalloc allowed). K-major tiled, SW128-preswizzled:
//   g_fused: [b][kt=16][m=4096][64ch]  (128B rows, swizzled within 1KB blocks)
//   g_wh   : [kt=16][o=512][64ch]      (shared fp16 weights, unscaled)
// ----------------------------------------------------------------------------
__device__ __half g_fused[8ull * 16ull * 4096ull * 64ull];
__device__ __half g_wh   [16ull * 512ull * 64ull];
__device__ __half g_scale_h[8 * 1024];               // per-(b,ch) gate fp16 (1.0 for LL)
__device__ float  g_sum  [8 * 768];                  // hf channel sums (zero-init; re-zeroed each call)
__device__ float  g_bns  [512];                      // folded BN scale
__device__ float  g_bnb  [512];                      // folded BN bias

// ----------------------------------------------------------------------------
// Helpers (baseline PTX only — no tcgen05 / no 'a'-gated features)
// ----------------------------------------------------------------------------
DI uint32_t sw128(uint32_t o) { return o ^ ((o >> 3) & 0x70u); }

DI uint32_t smem_u32(const void* p) {
    uint32_t a;
    asm("{ .reg .u64 t; cvta.to.shared.u64 t, %1; cvt.u32.u64 %0, t; }" : "=r"(a) : "l"(p));
    return a;
}
// global byte offset for (row, col2B) in a preswizzled [rows][64ch] tile
DI uint32_t tile_off(uint32_t row, uint32_t colbyte) {
    uint32_t off = row * 128u + colbyte;
    return (off & ~1023u) + sw128(off & 1023u);
}

DI void mbar_init(uint32_t mbar, uint32_t cnt) {
    asm volatile("mbarrier.init.shared.b64 [%0], %1;" :: "r"(mbar), "r"(cnt) : "memory");
}
DI void mbar_expect_tx(uint32_t mbar, uint32_t bytes) {
    asm volatile("mbarrier.arrive.expect_tx.shared.b64 _, [%0], %1;"
                 :: "r"(mbar), "r"(bytes) : "memory");
}
DI void mbar_arrive(uint32_t mbar) {
    asm volatile("mbarrier.arrive.shared.b64 _, [%0];" :: "r"(mbar) : "memory");
}
DI void mbar_wait(uint32_t mbar, uint32_t parity) {
    asm volatile(
        "{\n\t.reg .pred P1;\n\t"
        "LAB_WAIT_%=:\n\t"
        "mbarrier.try_wait.parity.acquire.cta.shared::cta.b64 P1, [%0], %1, 0x989680;\n\t"
        "@P1 bra.uni LAB_DONE_%=;\n\t"
        "bra.uni LAB_WAIT_%=;\n\t"
        "LAB_DONE_%=:\n\t}"
        :: "r"(mbar), "r"(parity) : "memory");
}
// 1-D bulk async copy global -> shared (sm_90 baseline; single thread issues)
DI void bulk_g2s(uint32_t dst, const void* src, uint32_t bytes, uint32_t mbar) {
    asm volatile(
        "cp.async.bulk.shared::cluster.global.mbarrier::complete_tx::bytes [%0], [%1], %2, [%3];"
        :: "r"(dst), "l"(__cvta_generic_to_global(src)), "r"(bytes), "r"(mbar) : "memory");
}

// ldmatrix x4: four 8x8 b16 matrices, lane-supplied row addresses
DI void ldsm4(uint32_t& r0, uint32_t& r1, uint32_t& r2, uint32_t& r3, uint32_t addr) {
    asm volatile("ldmatrix.sync.aligned.m8n8.x4.shared.b16 {%0,%1,%2,%3}, [%4];"
                 : "=r"(r0), "=r"(r1), "=r"(r2), "=r"(r3) : "r"(addr));
}

// fp16 HMMA with fp32 accumulate: D[16x8] += A[16x16] * B[16x8]
DI void mma16(float* c, const uint32_t* a, const uint32_t* b) {
    asm volatile(
        "mma.sync.aligned.m16n8k16.row.col.f32.f16.f16.f32 "
        "{%0,%1,%2,%3}, {%4,%5,%6,%7}, {%8,%9}, {%0,%1,%2,%3};"
        : "+f"(c[0]), "+f"(c[1]), "+f"(c[2]), "+f"(c[3])
        : "r"(a[0]), "r"(a[1]), "r"(a[2]), "r"(a[3]), "r"(b[0]), "r"(b[1]));
}

DI uint32_t h2mul(uint32_t a, uint32_t s) {
    uint32_t d;
    asm("mul.rn.f16x2 %0, %1, %2;" : "=r"(d) : "r"(a), "r"(s));
    return d;
}

// ----------------------------------------------------------------------------
// K1: Haar DWT -> preswizzled K-major g_fused + hf channel sums.
//     blockIdx.z==8 blocks instead convert conv_w -> preswizzled fp16 g_wh.
// grid (128 pos-tiles, 8 c-tiles, 9), 256 threads
// smem layout: sW[128][33]; element (r, pp) at column (pp + 5*(r>>3)) & 31.
// ----------------------------------------------------------------------------
__global__ __launch_bounds__(256) void k_wavelet(const float* __restrict__ x,
                                                 const float* __restrict__ conv_w) {
    const int tid = threadIdx.x;
    if (blockIdx.z == 8) {      // weight conversion: 262144 half2 over 1024 blocks
        int u  = (blockIdx.y * 128 + blockIdx.x) * 256 + tid;
        int kt = u >> 14;                       // 16384 half2 per kt tile (512 rows x 32)
        int r2 = u & 16383;
        int o  = r2 >> 5;
        int c2 = r2 & 31;
        int c  = kt * 64 + 2 * c2;
        __half2 v = __floats2half2_rn(conv_w[o * 1024 + c], conv_w[o * 1024 + c + 1]);
        char* base = reinterpret_cast<char*>(g_wh) + (size_t)kt * 512 * 128;
        *reinterpret_cast<__half2*>(base + tile_off(o, c2 * 4)) = v;
        return;
    }

    const int b = blockIdx.z, c0 = blockIdx.y * 32, p0 = blockIdx.x * 32;
    const int lane = tid & 31, w = tid >> 5;

    __shared__ float sW[128][33];

#pragma unroll
    for (int it = 0; it < 4; ++it) {
        int cc = it * 8 + w;
        int hw2 = p0 + lane;
        int h2 = hw2 >> 6, w2 = hw2 & 63;
        const float* xr = x + (((size_t)(b * 256 + c0 + cc) * 128 + 2 * h2) * 128 + 2 * w2);
        float2 t0 = *reinterpret_cast<const float2*>(xr);
        float2 t1 = *reinterpret_cast<const float2*>(xr + 128);
        float ll = 0.5f * (t0.x + t0.y + t1.x + t1.y);
        float lh = 0.5f * (t0.x + t0.y - t1.x - t1.y);
        float hl = 0.5f * (t0.x - t0.y + t1.x - t1.y);
        float hh = 0.5f * (t0.x - t0.y - t1.x + t1.y);
        sW[cc][(lane + 5 * it) & 31] = ll;                       // cc>>3 == it
        int rh = 32 + 3 * cc;
        sW[rh][(lane + 5 * (rh >> 3)) & 31] = lh;
        sW[rh + 1][(lane + 5 * ((rh + 1) >> 3)) & 31] = hl;
        sW[rh + 2][(lane + 5 * ((rh + 2) >> 3)) & 31] = hh;
    }
    __syncthreads();

    // hf channel sums: rows 32..127 = channel 3*c0 + rr, reduced by 4-thread groups
    {
        int q = tid & 3;
        {
            int rr = tid >> 2;                 // rr 0..63 -> rows 32..95
            int row = 32 + rr;
            int sh = 5 * (row >> 3);
            float v = 0.f;
#pragma unroll
            for (int t = 0; t < 8; t++) v += sW[row][(q * 8 + t + sh) & 31];
            v += __shfl_down_sync(0xffffffffu, v, 1);
            v += __shfl_down_sync(0xffffffffu, v, 2);
            if (q == 0) atomicAdd(&g_sum[b * 768 + 3 * c0 + rr], v);
        }
        if (tid < 128) {
            int rr = 64 + (tid >> 2);          // rows 96..127
            int row = 32 + rr;
            int sh = 5 * (row >> 3);
            float v = 0.f;
#pragma unroll
            for (int t = 0; t < 8; t++) v += sW[row][(q * 8 + t + sh) & 31];
            v += __shfl_down_sync(0xffffffffu, v, 1);
            v += __shfl_down_sync(0xffffffffu, v, 2);
            if (q == 0) atomicAdd(&g_sum[b * 768 + 3 * c0 + rr], v);
        }
    }

    // Write as 16B chunks (8 consecutive output channels); rows uniform per chunk.
#pragma unroll
    for (int it = 0; it < 2; ++it) {
        int wdx = it * 256 + tid;
        int pp = wdx >> 4, ci = wdx & 15;      // pos, chunk index
        int cl = ci * 8;
        int co = (pp + 5 * ci) & 31;           // stored column for rows 8ci..8ci+7
        float v[8];
#pragma unroll
        for (int t = 0; t < 8; t++) v[t] = sW[cl + t][co];
        __half2 h[4];
#pragma unroll
        for (int t = 0; t < 4; t++) h[t] = __floats2half2_rn(v[2 * t], v[2 * t + 1]);
        int col = (cl < 32) ? (c0 + cl) : (256 + 3 * c0 + (cl - 32));
        int m = p0 + pp;
        int kt = col >> 6, c6 = col & 63;
        char* base = reinterpret_cast<char*>(g_fused) + ((size_t)(b * 16 + kt) * 4096) * 128;
        const uint32_t* hw = reinterpret_cast<const uint32_t*>(h);
        uint4 pack;
        pack.x = hw[0];
        pack.y = hw[1];
        pack.z = hw[2];
        pack.w = hw[3];
        *reinterpret_cast<uint4*>(base + tile_off(m, c6 * 2)) = pack;
    }
}

// ----------------------------------------------------------------------------
// K2: blocks 0..7 = per-batch MLP gate (fp16) + g_sum re-zero;
//     block 8 = folded BN params
// ----------------------------------------------------------------------------
__global__ __launch_bounds__(256) void k_mlp(const float* __restrict__ w1, const float* __restrict__ w2,
                                             const float* __restrict__ gamma, const float* __restrict__ beta,
                                             const float* __restrict__ mean, const float* __restrict__ var) {
    int tid = threadIdx.x;
    int bx = blockIdx.x;
    if (bx == 8) {
        for (int o = tid; o < 512; o += 256) {
            float s = gamma[o] * rsqrtf(var[o] + 1e-5f);
            g_bns[o] = s;
            g_bnb[o] = beta[o] - mean[o] * s;
        }
        return;
    }
    int b = bx;
    __shared__ float s_mean[768];
    __shared__ float s_y1[48];
    for (int c = tid; c < 768; c += 256) s_mean[c] = g_sum[b * 768 + c] * (1.0f / 4096.0f);
    __syncthreads();
    int w = tid >> 5, lane = tid & 31;
#pragma unroll 1
    for (int i = 0; i < 6; i++) {
        int m = w + 8 * i;
        float acc = 0.f;
        for (int j = 0; j < 24; j++) {
            int c = lane + 32 * j;
            acc += s_mean[c] * w1[m * 768 + c];
        }
#pragma unroll
        for (int off = 16; off; off >>= 1) acc += __shfl_down_sync(0xffffffffu, acc, off);
        if (lane == 0) s_y1[m] = fmaxf(acc, 0.f);
    }
    __syncthreads();
    g_scale_h[b * 1024 + tid] = __float2half(1.0f);   // LL channels unscaled
    for (int c = tid; c < 768; c += 256) {
        float acc = 0.f;
#pragma unroll
        for (int m = 0; m < 48; m++) acc += s_y1[m] * w2[c * 48 + m];
        g_scale_h[b * 1024 + 256 + c] = __float2half_rn(1.0f / (1.0f + expf(-acc)));
    }
    // g_sum consumed above; zero this batch's slice for the next call
    for (int i = tid; i < 768; i += 256) g_sum[b * 768 + i] = 0.f;
}

// ----------------------------------------------------------------------------
// K4: fp16 mma.sync GEMM, 16 warps (4m x 4n, warp tile 32x32, low-reg),
//     gate folded into B fragments (skipped for LL kt<4), shared L2-resident
//     weights, ldmatrix.x4, cp.async.bulk free-running pipeline.
//     CTA tile 128M x 128N x 64K, 512 threads, 2 CTAs/SM,
//     smem-transposed epilogue + BN + SiLU. grid (4,32,8).
// ----------------------------------------------------------------------------
static constexpr int A_BYTES = 128 * 64 * 2;          // 16 KB
static constexpr int B_BYTES = 128 * 64 * 2;          // 16 KB
static constexpr int STAGE   = A_BYTES + B_BYTES;     // 32 KB
static constexpr int SC_OFF  = 64;                    // gate scales (2 KB) after mbars
static constexpr int SM_OFF  = 4096;                  // stage buffers
static constexpr int SMEM_SZ = SM_OFF + 3 * STAGE;    // 102400

__global__ __launch_bounds__(512, 2) void k_gemm(float* __restrict__ out) {
    extern __shared__ __align__(1024) char smem[];
    const uint32_t sb = smem_u32(smem);
    const int tid = threadIdx.x, lane = tid & 31, wid = tid >> 5;
    const int wm = wid & 3, wn = wid >> 2;            // warp grid 4(m) x 4(n)
    const int rq = lane >> 2, qq = lane & 3;
    const int b = blockIdx.z, m0 = blockIdx.y * 128, n0 = blockIdx.x * 128;

    if (tid == 0) {
#pragma unroll
        for (int s = 0; s < 3; s++) {
            mbar_init(sb + 8 * s, 1);        // full[s]
            mbar_init(sb + 32 + 8 * s, 16);  // empty[s]: one arrive per warp
        }
    }
    // preload gate scales for this batch: 1024 half = 512 u32
    {
        const uint32_t* src = reinterpret_cast<const uint32_t*>(g_scale_h + b * 1024);
        reinterpret_cast<uint32_t*>(smem + SC_OFF)[tid] = src[tid];
    }
    asm volatile("fence.proxy.async.shared::cta;" ::: "memory");
    __syncthreads();

    auto issue = [&](int st) {   // load k-stage st into slot st%3 (tid 0 only)
        int s = st % 3;
        uint32_t mb = sb + 8 * s;
        mbar_expect_tx(mb, STAGE);
        const char* srcA = reinterpret_cast<const char*>(g_fused) +
                           ((size_t)(b * 16 + st) * 4096 + m0) * 128;
        const char* srcB = reinterpret_cast<const char*>(g_wh) +
                           ((size_t)st * 512 + n0) * 128;
        bulk_g2s(sb + SM_OFF + s * STAGE, srcA, A_BYTES, mb);
        bulk_g2s(sb + SM_OFF + s * STAGE + A_BYTES, srcB, B_BYTES, mb);
    };
    if (tid == 0) { issue(0); issue(1); issue(2); }

    float acc[2][4][4];
#pragma unroll
    for (int i = 0; i < 2; i++)
#pragma unroll
        for (int j = 0; j < 4; j++)
#pragma unroll
            for (int r = 0; r < 4; r++) acc[i][j][r] = 0.f;

    // ldmatrix lane addressing (SW128-aware), constant per thread:
    const int x7  = lane & 7;
    const int khA = lane >> 4;                                 // k-half for A
    const int khB = (lane >> 3) & 1;                           // k-half for B
    const uint32_t rowA_off = (uint32_t)(wm * 32 + (lane & 15)) << 7;
    const uint32_t rowB_off = (uint32_t)(wn * 32 + (lane & 7) + ((lane >> 4) << 3)) << 7;
    const char* scp = smem + SC_OFF + qq * 4;                  // per-thread scale base

#pragma unroll 1
    for (int kt = 0; kt < 16; ++kt) {
        int s = kt % 3;
        mbar_wait(sb + 8 * s, (kt / 3) & 1);              // full[s]

        const uint32_t baseA = sb + SM_OFF + s * STAGE + rowA_off;
        const uint32_t baseB = sb + SM_OFF + s * STAGE + A_BYTES + rowB_off;
        const char* sck = scp + kt * 128;
        const bool gated = (kt >= 4);                      // LL kt tiles: gate == 1.0

#pragma unroll
        for (int ks = 0; ks < 4; ++ks) {
            const uint32_t cA = (uint32_t)(((2 * ks + khA) ^ x7) << 4);
            const uint32_t cB = (uint32_t)(((2 * ks + khB) ^ x7) << 4);
            uint32_t a[2][4], bf[4][2];
#pragma unroll
            for (int i = 0; i < 2; i++)
                ldsm4(a[i][0], a[i][1], a[i][2], a[i][3], baseA + (i << 11) + cA);
            ldsm4(bf[0][0], bf[0][1], bf[1][0], bf[1][1], baseB + cB);
            ldsm4(bf[2][0], bf[2][1], bf[3][0], bf[3][1], baseB + (1 << 11) + cB);
            if (gated) {
                // gate: k = kt*64 + ks*16 + g*8 + 2qq + {0,1}; reg g selects +16B
                uint32_t s0 = *reinterpret_cast<const uint32_t*>(sck + ks * 32);
                uint32_t s1 = *reinterpret_cast<const uint32_t*>(sck + ks * 32 + 16);
#pragma unroll
                for (int j = 0; j < 4; j++) {
                    bf[j][0] = h2mul(bf[j][0], s0);
                    bf[j][1] = h2mul(bf[j][1], s1);
                }
            }
#pragma unroll
            for (int i = 0; i < 2; i++)
#pragma unroll
                for (int j = 0; j < 4; j++) mma16(acc[i][j], a[i], bf[j]);
        }

        if (lane == 0) mbar_arrive(sb + 32 + 8 * s);      // warp done with slot s
        if (kt < 13 && tid == 0) {
            mbar_wait(sb + 32 + 8 * s, (kt / 3) & 1);     // all warps consumed slot s
            issue(kt + 3);
        }
    }
    __syncthreads();   // all warps out of the mainloop before smem reuse

    // ---- epilogue: transpose through smem, fused BN + SiLU, coalesced STG ----
    float* eP = reinterpret_cast<float*>(smem + SM_OFF);   // [n 128][m 128], stride 132
#pragma unroll
    for (int i = 0; i < 2; i++) {
        int m = wm * 32 + i * 16 + rq;
#pragma unroll
        for (int j = 0; j < 4; j++) {
            int n = wn * 32 + j * 8 + 2 * qq;
            eP[n * 132 + m]           = acc[i][j][0];
            eP[(n + 1) * 132 + m]     = acc[i][j][1];
            eP[n * 132 + m + 8]       = acc[i][j][2];
            eP[(n + 1) * 132 + m + 8] = acc[i][j][3];
        }
    }
    __syncthreads();

#pragma unroll 1
    for (int idx = tid; idx < 128 * 32; idx += 512) {
        int row = idx >> 5;            // local output channel
        int seg = idx & 31;            // 4-float segment along m
        float4 v = *reinterpret_cast<const float4*>(eP + row * 132 + seg * 4);
        int oc = n0 + row;
        float s = g_bns[oc], t = g_bnb[oc];
        float z0 = v.x * s + t, z1 = v.y * s + t, z2 = v.z * s + t, z3 = v.w * s + t;
        float4 o4;
        o4.x = z0 / (1.0f + __expf(-z0));
        o4.y = z1 / (1.0f + __expf(-z1));
        o4.z = z2 / (1.0f + __expf(-z2));
        o4.w = z3 / (1.0f + __expf(-z3));
        *reinterpret_cast<float4*>(out + (((size_t)(b * 512 + oc)) << 12) + m0 + seg * 4) = o4;
    }
}

// ----------------------------------------------------------------------------
// Launch (3 kernels per call; g_sum starts zeroed: zero-init + k_mlp tail)
// ----------------------------------------------------------------------------
extern "C" void kernel_launch(void* const* d_in, const int* in_sizes, int n_in,
                              void* d_out, int out_size) {
    const float* x      = (const float*)d_in[0];
    const float* w1     = (const float*)d_in[1];
    const float* w2     = (const float*)d_in[2];
    const float* conv_w = (const float*)d_in[3];
    const float* gamma  = (const float*)d_in[4];
    const float* beta   = (const float*)d_in[5];
    const float* mean   = (const float*)d_in[6];
    const float* var    = (const float*)d_in[7];
    float* out = (float*)d_out;
    (void)in_sizes; (void)n_in; (void)out_size;

    cudaFuncSetAttribute(k_gemm, cudaFuncAttributeMaxDynamicSharedMemorySize, SMEM_SZ);

    k_wavelet<<<dim3(128, 8, 9), 256>>>(x, conv_w);
    k_mlp<<<9, 256>>>(w1, w2, gamma, beta, mean, var);
    k_gemm<<<dim3(4, 32, 8), 512, SMEM_SZ>>>(out);
}

// round 15
// speedup vs baseline: 1.0112x; 1.0112x over previous
#include <cuda_runtime.h>
#include <cuda_fp16.h>
#include <cstdint>
#include <math.h>

#define DI __device__ __forceinline__

// ----------------------------------------------------------------------------
// Device scratch (no cudaMalloc allowed). K-major tiled, SW128-preswizzled:
//   g_fused: [b][kt=16][m=4096][64ch]  (128B rows, swizzled within 1KB blocks)
//   g_wh   : [kt=16][o=512][64ch]      (shared fp16 weights, unscaled)
// ----------------------------------------------------------------------------
__device__ __half g_fused[8ull * 16ull * 4096ull * 64ull];
__device__ __half g_wh   [16ull * 512ull * 64ull];
__device__ __half g_scale_h[8 * 1024];               // per-(b,ch) gate fp16 (1.0 for LL)
__device__ float  g_sum  [8 * 768];                  // hf channel sums (zero-init; re-zeroed each call)
__device__ float  g_bns  [512];                      // folded BN scale
__device__ float  g_bnb  [512];                      // folded BN bias

// ----------------------------------------------------------------------------
// Helpers (baseline PTX only — no tcgen05 / no 'a'-gated features)
// ----------------------------------------------------------------------------
DI uint32_t sw128(uint32_t o) { return o ^ ((o >> 3) & 0x70u); }

DI uint32_t smem_u32(const void* p) {
    uint32_t a;
    asm("{ .reg .u64 t; cvta.to.shared.u64 t, %1; cvt.u32.u64 %0, t; }" : "=r"(a) : "l"(p));
    return a;
}
// global byte offset for (row, col2B) in a preswizzled [rows][64ch] tile
DI uint32_t tile_off(uint32_t row, uint32_t colbyte) {
    uint32_t off = row * 128u + colbyte;
    return (off & ~1023u) + sw128(off & 1023u);
}

DI void mbar_init(uint32_t mbar, uint32_t cnt) {
    asm volatile("mbarrier.init.shared.b64 [%0], %1;" :: "r"(mbar), "r"(cnt) : "memory");
}
DI void mbar_expect_tx(uint32_t mbar, uint32_t bytes) {
    asm volatile("mbarrier.arrive.expect_tx.shared.b64 _, [%0], %1;"
                 :: "r"(mbar), "r"(bytes) : "memory");
}
DI void mbar_arrive(uint32_t mbar) {
    asm volatile("mbarrier.arrive.shared.b64 _, [%0];" :: "r"(mbar) : "memory");
}
DI void mbar_wait(uint32_t mbar, uint32_t parity) {
    asm volatile(
        "{\n\t.reg .pred P1;\n\t"
        "LAB_WAIT_%=:\n\t"
        "mbarrier.try_wait.parity.acquire.cta.shared::cta.b64 P1, [%0], %1, 0x989680;\n\t"
        "@P1 bra.uni LAB_DONE_%=;\n\t"
        "bra.uni LAB_WAIT_%=;\n\t"
        "LAB_DONE_%=:\n\t}"
        :: "r"(mbar), "r"(parity) : "memory");
}
// 1-D bulk async copy global -> shared (sm_90 baseline; single thread issues)
DI void bulk_g2s(uint32_t dst, const void* src, uint32_t bytes, uint32_t mbar) {
    asm volatile(
        "cp.async.bulk.shared::cluster.global.mbarrier::complete_tx::bytes [%0], [%1], %2, [%3];"
        :: "r"(dst), "l"(__cvta_generic_to_global(src)), "r"(bytes), "r"(mbar) : "memory");
}

// ldmatrix x4: four 8x8 b16 matrices, lane-supplied row addresses
DI void ldsm4(uint32_t& r0, uint32_t& r1, uint32_t& r2, uint32_t& r3, uint32_t addr) {
    asm volatile("ldmatrix.sync.aligned.m8n8.x4.shared.b16 {%0,%1,%2,%3}, [%4];"
                 : "=r"(r0), "=r"(r1), "=r"(r2), "=r"(r3) : "r"(addr));
}

// fp16 HMMA with fp32 accumulate: D[16x8] += A[16x16] * B[16x8]
DI void mma16(float* c, const uint32_t* a, const uint32_t* b) {
    asm volatile(
        "mma.sync.aligned.m16n8k16.row.col.f32.f16.f16.f32 "
        "{%0,%1,%2,%3}, {%4,%5,%6,%7}, {%8,%9}, {%0,%1,%2,%3};"
        : "+f"(c[0]), "+f"(c[1]), "+f"(c[2]), "+f"(c[3])
        : "r"(a[0]), "r"(a[1]), "r"(a[2]), "r"(a[3]), "r"(b[0]), "r"(b[1]));
}

DI uint32_t h2mul(uint32_t a, uint32_t s) {
    uint32_t d;
    asm("mul.rn.f16x2 %0, %1, %2;" : "=r"(d) : "r"(a), "r"(s));
    return d;
}

// ----------------------------------------------------------------------------
// K1: Haar DWT -> preswizzled K-major g_fused + hf channel sums.
//     blockIdx.z==8 blocks instead convert conv_w -> preswizzled fp16 g_wh.
// grid (128 pos-tiles, 8 c-tiles, 9), 256 threads
// smem layout: sW[128][33]; element (r, pp) at column (pp + 5*(r>>3)) & 31.
// ----------------------------------------------------------------------------
__global__ __launch_bounds__(256) void k_wavelet(const float* __restrict__ x,
                                                 const float* __restrict__ conv_w) {
    const int tid = threadIdx.x;
    if (blockIdx.z == 8) {      // weight conversion: 262144 half2 over 1024 blocks
        int u  = (blockIdx.y * 128 + blockIdx.x) * 256 + tid;
        int kt = u >> 14;                       // 16384 half2 per kt tile (512 rows x 32)
        int r2 = u & 16383;
        int o  = r2 >> 5;
        int c2 = r2 & 31;
        int c  = kt * 64 + 2 * c2;
        __half2 v = __floats2half2_rn(conv_w[o * 1024 + c], conv_w[o * 1024 + c + 1]);
        char* base = reinterpret_cast<char*>(g_wh) + (size_t)kt * 512 * 128;
        *reinterpret_cast<__half2*>(base + tile_off(o, c2 * 4)) = v;
        return;
    }

    const int b = blockIdx.z, c0 = blockIdx.y * 32, p0 = blockIdx.x * 32;
    const int lane = tid & 31, w = tid >> 5;

    __shared__ float sW[128][33];

#pragma unroll
    for (int it = 0; it < 4; ++it) {
        int cc = it * 8 + w;
        int hw2 = p0 + lane;
        int h2 = hw2 >> 6, w2 = hw2 & 63;
        const float* xr = x + (((size_t)(b * 256 + c0 + cc) * 128 + 2 * h2) * 128 + 2 * w2);
        float2 t0 = *reinterpret_cast<const float2*>(xr);
        float2 t1 = *reinterpret_cast<const float2*>(xr + 128);
        float ll = 0.5f * (t0.x + t0.y + t1.x + t1.y);
        float lh = 0.5f * (t0.x + t0.y - t1.x - t1.y);
        float hl = 0.5f * (t0.x - t0.y + t1.x - t1.y);
        float hh = 0.5f * (t0.x - t0.y - t1.x + t1.y);
        sW[cc][(lane + 5 * it) & 31] = ll;                       // cc>>3 == it
        int rh = 32 + 3 * cc;
        sW[rh][(lane + 5 * (rh >> 3)) & 31] = lh;
        sW[rh + 1][(lane + 5 * ((rh + 1) >> 3)) & 31] = hl;
        sW[rh + 2][(lane + 5 * ((rh + 2) >> 3)) & 31] = hh;
    }
    __syncthreads();

    // hf channel sums: rows 32..127 = channel 3*c0 + rr, reduced by 4-thread groups
    {
        int q = tid & 3;
        {
            int rr = tid >> 2;                 // rr 0..63 -> rows 32..95
            int row = 32 + rr;
            int sh = 5 * (row >> 3);
            float v = 0.f;
#pragma unroll
            for (int t = 0; t < 8; t++) v += sW[row][(q * 8 + t + sh) & 31];
            v += __shfl_down_sync(0xffffffffu, v, 1);
            v += __shfl_down_sync(0xffffffffu, v, 2);
            if (q == 0) atomicAdd(&g_sum[b * 768 + 3 * c0 + rr], v);
        }
        if (tid < 128) {
            int rr = 64 + (tid >> 2);          // rows 96..127
            int row = 32 + rr;
            int sh = 5 * (row >> 3);
            float v = 0.f;
#pragma unroll
            for (int t = 0; t < 8; t++) v += sW[row][(q * 8 + t + sh) & 31];
            v += __shfl_down_sync(0xffffffffu, v, 1);
            v += __shfl_down_sync(0xffffffffu, v, 2);
            if (q == 0) atomicAdd(&g_sum[b * 768 + 3 * c0 + rr], v);
        }
    }

    // Write as 16B chunks (8 consecutive output channels); rows uniform per chunk.
#pragma unroll
    for (int it = 0; it < 2; ++it) {
        int wdx = it * 256 + tid;
        int pp = wdx >> 4, ci = wdx & 15;      // pos, chunk index
        int cl = ci * 8;
        int co = (pp + 5 * ci) & 31;           // stored column for rows 8ci..8ci+7
        float v[8];
#pragma unroll
        for (int t = 0; t < 8; t++) v[t] = sW[cl + t][co];
        __half2 h[4];
#pragma unroll
        for (int t = 0; t < 4; t++) h[t] = __floats2half2_rn(v[2 * t], v[2 * t + 1]);
        int col = (cl < 32) ? (c0 + cl) : (256 + 3 * c0 + (cl - 32));
        int m = p0 + pp;
        int kt = col >> 6, c6 = col & 63;
        char* base = reinterpret_cast<char*>(g_fused) + ((size_t)(b * 16 + kt) * 4096) * 128;
        const uint32_t* hw = reinterpret_cast<const uint32_t*>(h);
        uint4 pack;
        pack.x = hw[0];
        pack.y = hw[1];
        pack.z = hw[2];
        pack.w = hw[3];
        *reinterpret_cast<uint4*>(base + tile_off(m, c6 * 2)) = pack;
    }
}

// ----------------------------------------------------------------------------
// K2: blocks 0..7 = per-batch MLP gate (fp16) + g_sum re-zero;
//     block 8 = folded BN params
// ----------------------------------------------------------------------------
__global__ __launch_bounds__(256) void k_mlp(const float* __restrict__ w1, const float* __restrict__ w2,
                                             const float* __restrict__ gamma, const float* __restrict__ beta,
                                             const float* __restrict__ mean, const float* __restrict__ var) {
    int tid = threadIdx.x;
    int bx = blockIdx.x;
    if (bx == 8) {
        for (int o = tid; o < 512; o += 256) {
            float s = gamma[o] * rsqrtf(var[o] + 1e-5f);
            g_bns[o] = s;
            g_bnb[o] = beta[o] - mean[o] * s;
        }
        return;
    }
    int b = bx;
    __shared__ float s_mean[768];
    __shared__ float s_y1[48];
    for (int c = tid; c < 768; c += 256) s_mean[c] = g_sum[b * 768 + c] * (1.0f / 4096.0f);
    __syncthreads();
    int w = tid >> 5, lane = tid & 31;
#pragma unroll 1
    for (int i = 0; i < 6; i++) {
        int m = w + 8 * i;
        float acc = 0.f;
        for (int j = 0; j < 24; j++) {
            int c = lane + 32 * j;
            acc += s_mean[c] * w1[m * 768 + c];
        }
#pragma unroll
        for (int off = 16; off; off >>= 1) acc += __shfl_down_sync(0xffffffffu, acc, off);
        if (lane == 0) s_y1[m] = fmaxf(acc, 0.f);
    }
    __syncthreads();
    g_scale_h[b * 1024 + tid] = __float2half(1.0f);   // LL channels unscaled
    for (int c = tid; c < 768; c += 256) {
        float acc = 0.f;
#pragma unroll
        for (int m = 0; m < 48; m++) acc += s_y1[m] * w2[c * 48 + m];
        g_scale_h[b * 1024 + 256 + c] = __float2half_rn(1.0f / (1.0f + expf(-acc)));
    }
    // g_sum consumed above; zero this batch's slice for the next call
    for (int i = tid; i < 768; i += 256) g_sum[b * 768 + i] = 0.f;
}

// ----------------------------------------------------------------------------
// K4: fp16 mma.sync GEMM (round-13 config: 8 warps, 2m x 4n, 64x32 warp tile),
//     gate folded into double-buffered B fragments, SKIPPED for LL kt<4,
//     shared L2-resident weights, ldmatrix.x4, cp.async.bulk free-running
//     pipeline. CTA tile 128M x 128N x 64K, 256 threads, 2 CTAs/SM,
//     smem-transposed epilogue + BN + SiLU. grid (4,32,8).
// ----------------------------------------------------------------------------
static constexpr int A_BYTES = 128 * 64 * 2;          // 16 KB
static constexpr int B_BYTES = 128 * 64 * 2;          // 16 KB
static constexpr int STAGE   = A_BYTES + B_BYTES;     // 32 KB
static constexpr int SC_OFF  = 64;                    // gate scales (2 KB) after mbars
static constexpr int SM_OFF  = 4096;                  // stage buffers
static constexpr int SMEM_SZ = SM_OFF + 3 * STAGE;    // 102400

__global__ __launch_bounds__(256, 2) void k_gemm(float* __restrict__ out) {
    extern __shared__ __align__(1024) char smem[];
    const uint32_t sb = smem_u32(smem);
    const int tid = threadIdx.x, lane = tid & 31, wid = tid >> 5;
    const int wm = wid & 1, wn = wid >> 1;            // warp grid 2(m) x 4(n)
    const int rq = lane >> 2, qq = lane & 3;
    const int b = blockIdx.z, m0 = blockIdx.y * 128, n0 = blockIdx.x * 128;

    if (tid == 0) {
#pragma unroll
        for (int s = 0; s < 3; s++) {
            mbar_init(sb + 8 * s, 1);        // full[s]
            mbar_init(sb + 32 + 8 * s, 8);   // empty[s]: one arrive per warp
        }
    }
    // preload gate scales for this batch: 1024 half = 512 u32
    {
        const uint32_t* src = reinterpret_cast<const uint32_t*>(g_scale_h + b * 1024);
        uint32_t* dst = reinterpret_cast<uint32_t*>(smem + SC_OFF);
        dst[tid] = src[tid];
        dst[tid + 256] = src[tid + 256];
    }
    asm volatile("fence.proxy.async.shared::cta;" ::: "memory");
    __syncthreads();

    auto issue = [&](int st) {   // load k-stage st into slot st%3 (tid 0 only)
        int s = st % 3;
        uint32_t mb = sb + 8 * s;
        mbar_expect_tx(mb, STAGE);
        const char* srcA = reinterpret_cast<const char*>(g_fused) +
                           ((size_t)(b * 16 + st) * 4096 + m0) * 128;
        const char* srcB = reinterpret_cast<const char*>(g_wh) +
                           ((size_t)st * 512 + n0) * 128;
        bulk_g2s(sb + SM_OFF + s * STAGE, srcA, A_BYTES, mb);
        bulk_g2s(sb + SM_OFF + s * STAGE + A_BYTES, srcB, B_BYTES, mb);
    };
    if (tid == 0) { issue(0); issue(1); issue(2); }

    float acc[4][4][4];
#pragma unroll
    for (int i = 0; i < 4; i++)
#pragma unroll
        for (int j = 0; j < 4; j++)
#pragma unroll
            for (int r = 0; r < 4; r++) acc[i][j][r] = 0.f;

    // ldmatrix lane addressing (SW128-aware), constant per thread:
    const int x7  = lane & 7;
    const int khA = lane >> 4;                                 // k-half for A
    const int khB = (lane >> 3) & 1;                           // k-half for B
    const uint32_t rowA_off = (uint32_t)(wm * 64 + (lane & 15)) << 7;
    const uint32_t rowB_off = (uint32_t)(wn * 32 + (lane & 7) + ((lane >> 4) << 3)) << 7;
    const char* scp = smem + SC_OFF + qq * 4;                  // per-thread scale base

#pragma unroll 1
    for (int kt = 0; kt < 16; ++kt) {
        int s = kt % 3;
        mbar_wait(sb + 8 * s, (kt / 3) & 1);              // full[s]

        const uint32_t baseA = sb + SM_OFF + s * STAGE + rowA_off;
        const uint32_t baseB = sb + SM_OFF + s * STAGE + A_BYTES + rowB_off;
        const char* sck = scp + kt * 128;
        const bool gated = (kt >= 4);                      // LL kt tiles: gate == 1.0

        // double-buffered, gate-scaled B fragments
        uint32_t bf0[4][2], bf1[4][2];
        auto loadB = [&](int ks, uint32_t (&bf)[4][2]) {
            const uint32_t cB = (uint32_t)(((2 * ks + khB) ^ x7) << 4);
            ldsm4(bf[0][0], bf[0][1], bf[1][0], bf[1][1], baseB + cB);
            ldsm4(bf[2][0], bf[2][1], bf[3][0], bf[3][1], baseB + (1 << 11) + cB);
            if (gated) {
                // gate: k = kt*64 + ks*16 + g*8 + 2qq + {0,1}; reg g selects +16B
                uint32_t s0 = *reinterpret_cast<const uint32_t*>(sck + ks * 32);
                uint32_t s1 = *reinterpret_cast<const uint32_t*>(sck + ks * 32 + 16);
#pragma unroll
                for (int j = 0; j < 4; j++) {
                    bf[j][0] = h2mul(bf[j][0], s0);
                    bf[j][1] = h2mul(bf[j][1], s1);
                }
            }
        };
        loadB(0, bf0);

#pragma unroll
        for (int ks = 0; ks < 4; ++ks) {
            const uint32_t cA = (uint32_t)(((2 * ks + khA) ^ x7) << 4);
            uint32_t a[4][4];
#pragma unroll
            for (int i = 0; i < 4; i++)
                ldsm4(a[i][0], a[i][1], a[i][2], a[i][3], baseA + (i << 11) + cA);
            if (ks < 3) loadB(ks + 1, (ks & 1) ? bf0 : bf1);
            uint32_t (&cur)[4][2] = (ks & 1) ? bf1 : bf0;
#pragma unroll
            for (int i = 0; i < 4; i++)
#pragma unroll
                for (int j = 0; j < 4; j++) mma16(acc[i][j], a[i], cur[j]);
        }

        if (lane == 0) mbar_arrive(sb + 32 + 8 * s);      // warp done with slot s
        if (kt < 13 && tid == 0) {
            mbar_wait(sb + 32 + 8 * s, (kt / 3) & 1);     // all warps consumed slot s
            issue(kt + 3);
        }
    }
    __syncthreads();   // all warps out of the mainloop before smem reuse

    // ---- epilogue: transpose through smem, fused BN + SiLU, coalesced STG ----
    float* eP = reinterpret_cast<float*>(smem + SM_OFF);   // [n 128][m 128], stride 132
#pragma unroll
    for (int i = 0; i < 4; i++) {
        int m = wm * 64 + i * 16 + rq;
#pragma unroll
        for (int j = 0; j < 4; j++) {
            int n = wn * 32 + j * 8 + 2 * qq;
            eP[n * 132 + m]           = acc[i][j][0];
            eP[(n + 1) * 132 + m]     = acc[i][j][1];
            eP[n * 132 + m + 8]       = acc[i][j][2];
            eP[(n + 1) * 132 + m + 8] = acc[i][j][3];
        }
    }
    __syncthreads();

#pragma unroll 1
    for (int idx = tid; idx < 128 * 32; idx += 256) {
        int row = idx >> 5;            // local output channel (uniform per warp)
        int seg = idx & 31;            // 4-float segment along m
        float4 v = *reinterpret_cast<const float4*>(eP + row * 132 + seg * 4);
        int oc = n0 + row;
        float s = g_bns[oc], t = g_bnb[oc];
        float z0 = v.x * s + t, z1 = v.y * s + t, z2 = v.z * s + t, z3 = v.w * s + t;
        float4 o4;
        o4.x = z0 / (1.0f + __expf(-z0));
        o4.y = z1 / (1.0f + __expf(-z1));
        o4.z = z2 / (1.0f + __expf(-z2));
        o4.w = z3 / (1.0f + __expf(-z3));
        *reinterpret_cast<float4*>(out + (((size_t)(b * 512 + oc)) << 12) + m0 + seg * 4) = o4;
    }
}

// ----------------------------------------------------------------------------
// Launch (3 kernels per call; g_sum starts zeroed: zero-init + k_mlp tail)
// ----------------------------------------------------------------------------
extern "C" void kernel_launch(void* const* d_in, const int* in_sizes, int n_in,
                              void* d_out, int out_size) {
    const float* x      = (const float*)d_in[0];
    const float* w1     = (const float*)d_in[1];
    const float* w2     = (const float*)d_in[2];
    const float* conv_w = (const float*)d_in[3];
    const float* gamma  = (const float*)d_in[4];
    const float* beta   = (const float*)d_in[5];
    const float* mean   = (const float*)d_in[6];
    const float* var    = (const float*)d_in[7];
    float* out = (float*)d_out;
    (void)in_sizes; (void)n_in; (void)out_size;

    cudaFuncSetAttribute(k_gemm, cudaFuncAttributeMaxDynamicSharedMemorySize, SMEM_SZ);

    k_wavelet<<<dim3(128, 8, 9), 256>>>(x, conv_w);
    k_mlp<<<9, 256>>>(w1, w2, gamma, beta, mean, var);
    k_gemm<<<dim3(4, 32, 8), 256, SMEM_SZ>>>(out);
}

// round 16
// speedup vs baseline: 1.0703x; 1.0585x over previous
#include <cuda_runtime.h>
#include <cuda_fp16.h>
#include <cstdint>
#include <math.h>

#define DI __device__ __forceinline__

// ----------------------------------------------------------------------------
// Device scratch (no cudaMalloc allowed). K-major tiled, SW128-preswizzled:
//   g_fused: [b][kt=16][m=4096][64ch]  (128B rows, swizzled within 1KB blocks)
//   g_wh   : [kt=16][o=512][64ch]      (shared fp16 weights, unscaled)
// ----------------------------------------------------------------------------
__device__ __half g_fused[8ull * 16ull * 4096ull * 64ull];
__device__ __half g_wh   [16ull * 512ull * 64ull];
__device__ __half g_scale_h[8 * 1024];               // per-(b,ch) gate fp16 (1.0 for LL)
__device__ float  g_sum  [8 * 768];                  // hf channel sums (zero-init; re-zeroed each call)
__device__ float  g_bns  [512];                      // folded BN scale
__device__ float  g_bnb  [512];                      // folded BN bias

// ----------------------------------------------------------------------------
// Helpers (baseline PTX only — no tcgen05 / no 'a'-gated features)
// ----------------------------------------------------------------------------
DI uint32_t sw128(uint32_t o) { return o ^ ((o >> 3) & 0x70u); }

DI uint32_t smem_u32(const void* p) {
    uint32_t a;
    asm("{ .reg .u64 t; cvta.to.shared.u64 t, %1; cvt.u32.u64 %0, t; }" : "=r"(a) : "l"(p));
    return a;
}
// global byte offset for (row, col2B) in a preswizzled [rows][64ch] tile
DI uint32_t tile_off(uint32_t row, uint32_t colbyte) {
    uint32_t off = row * 128u + colbyte;
    return (off & ~1023u) + sw128(off & 1023u);
}

DI void mbar_init(uint32_t mbar, uint32_t cnt) {
    asm volatile("mbarrier.init.shared.b64 [%0], %1;" :: "r"(mbar), "r"(cnt) : "memory");
}
DI void mbar_expect_tx(uint32_t mbar, uint32_t bytes) {
    asm volatile("mbarrier.arrive.expect_tx.shared.b64 _, [%0], %1;"
                 :: "r"(mbar), "r"(bytes) : "memory");
}
DI void mbar_arrive(uint32_t mbar) {
    asm volatile("mbarrier.arrive.shared.b64 _, [%0];" :: "r"(mbar) : "memory");
}
DI void mbar_wait(uint32_t mbar, uint32_t parity) {
    asm volatile(
        "{\n\t.reg .pred P1;\n\t"
        "LAB_WAIT_%=:\n\t"
        "mbarrier.try_wait.parity.acquire.cta.shared::cta.b64 P1, [%0], %1, 0x989680;\n\t"
        "@P1 bra.uni LAB_DONE_%=;\n\t"
        "bra.uni LAB_WAIT_%=;\n\t"
        "LAB_DONE_%=:\n\t}"
        :: "r"(mbar), "r"(parity) : "memory");
}
// 1-D bulk async copy global -> shared (sm_90 baseline; single thread issues)
DI void bulk_g2s(uint32_t dst, const void* src, uint32_t bytes, uint32_t mbar) {
    asm volatile(
        "cp.async.bulk.shared::cluster.global.mbarrier::complete_tx::bytes [%0], [%1], %2, [%3];"
        :: "r"(dst), "l"(__cvta_generic_to_global(src)), "r"(bytes), "r"(mbar) : "memory");
}

// ldmatrix x4: four 8x8 b16 matrices, lane-supplied row addresses
DI void ldsm4(uint32_t& r0, uint32_t& r1, uint32_t& r2, uint32_t& r3, uint32_t addr) {
    asm volatile("ldmatrix.sync.aligned.m8n8.x4.shared.b16 {%0,%1,%2,%3}, [%4];"
                 : "=r"(r0), "=r"(r1), "=r"(r2), "=r"(r3) : "r"(addr));
}

// fp16 HMMA with fp32 accumulate: D[16x8] += A[16x16] * B[16x8]
DI void mma16(float* c, const uint32_t* a, const uint32_t* b) {
    asm volatile(
        "mma.sync.aligned.m16n8k16.row.col.f32.f16.f16.f32 "
        "{%0,%1,%2,%3}, {%4,%5,%6,%7}, {%8,%9}, {%0,%1,%2,%3};"
        : "+f"(c[0]), "+f"(c[1]), "+f"(c[2]), "+f"(c[3])
        : "r"(a[0]), "r"(a[1]), "r"(a[2]), "r"(a[3]), "r"(b[0]), "r"(b[1]));
}

DI uint32_t h2mul(uint32_t a, uint32_t s) {
    uint32_t d;
    asm("mul.rn.f16x2 %0, %1, %2;" : "=r"(d) : "r"(a), "r"(s));
    return d;
}

// ----------------------------------------------------------------------------
// K1: Haar DWT -> preswizzled K-major g_fused + hf channel sums.
//     blockIdx.z==8 blocks instead convert conv_w -> preswizzled fp16 g_wh.
// grid (128 pos-tiles, 8 c-tiles, 9), 256 threads
// smem layout: sW[128][33]; element (r, pp) at column (pp + 5*(r>>3)) & 31.
// ----------------------------------------------------------------------------
__global__ __launch_bounds__(256) void k_wavelet(const float* __restrict__ x,
                                                 const float* __restrict__ conv_w) {
    const int tid = threadIdx.x;
    if (blockIdx.z == 8) {      // weight conversion: 262144 half2 over 1024 blocks
        int u  = (blockIdx.y * 128 + blockIdx.x) * 256 + tid;
        int kt = u >> 14;                       // 16384 half2 per kt tile (512 rows x 32)
        int r2 = u & 16383;
        int o  = r2 >> 5;
        int c2 = r2 & 31;
        int c  = kt * 64 + 2 * c2;
        __half2 v = __floats2half2_rn(conv_w[o * 1024 + c], conv_w[o * 1024 + c + 1]);
        char* base = reinterpret_cast<char*>(g_wh) + (size_t)kt * 512 * 128;
        *reinterpret_cast<__half2*>(base + tile_off(o, c2 * 4)) = v;
        return;
    }

    const int b = blockIdx.z, c0 = blockIdx.y * 32, p0 = blockIdx.x * 32;
    const int lane = tid & 31, w = tid >> 5;

    __shared__ float sW[128][33];

#pragma unroll
    for (int it = 0; it < 4; ++it) {
        int cc = it * 8 + w;
        int hw2 = p0 + lane;
        int h2 = hw2 >> 6, w2 = hw2 & 63;
        const float* xr = x + (((size_t)(b * 256 + c0 + cc) * 128 + 2 * h2) * 128 + 2 * w2);
        float2 t0 = *reinterpret_cast<const float2*>(xr);
        float2 t1 = *reinterpret_cast<const float2*>(xr + 128);
        float ll = 0.5f * (t0.x + t0.y + t1.x + t1.y);
        float lh = 0.5f * (t0.x + t0.y - t1.x - t1.y);
        float hl = 0.5f * (t0.x - t0.y + t1.x - t1.y);
        float hh = 0.5f * (t0.x - t0.y - t1.x + t1.y);
        sW[cc][(lane + 5 * it) & 31] = ll;                       // cc>>3 == it
        int rh = 32 + 3 * cc;
        sW[rh][(lane + 5 * (rh >> 3)) & 31] = lh;
        sW[rh + 1][(lane + 5 * ((rh + 1) >> 3)) & 31] = hl;
        sW[rh + 2][(lane + 5 * ((rh + 2) >> 3)) & 31] = hh;
    }
    __syncthreads();

    // hf channel sums: rows 32..127 = channel 3*c0 + rr, reduced by 4-thread groups
    {
        int q = tid & 3;
        {
            int rr = tid >> 2;                 // rr 0..63 -> rows 32..95
            int row = 32 + rr;
            int sh = 5 * (row >> 3);
            float v = 0.f;
#pragma unroll
            for (int t = 0; t < 8; t++) v += sW[row][(q * 8 + t + sh) & 31];
            v += __shfl_down_sync(0xffffffffu, v, 1);
            v += __shfl_down_sync(0xffffffffu, v, 2);
            if (q == 0) atomicAdd(&g_sum[b * 768 + 3 * c0 + rr], v);
        }
        if (tid < 128) {
            int rr = 64 + (tid >> 2);          // rows 96..127
            int row = 32 + rr;
            int sh = 5 * (row >> 3);
            float v = 0.f;
#pragma unroll
            for (int t = 0; t < 8; t++) v += sW[row][(q * 8 + t + sh) & 31];
            v += __shfl_down_sync(0xffffffffu, v, 1);
            v += __shfl_down_sync(0xffffffffu, v, 2);
            if (q == 0) atomicAdd(&g_sum[b * 768 + 3 * c0 + rr], v);
        }
    }

    // Write as 16B chunks (8 consecutive output channels); rows uniform per chunk.
#pragma unroll
    for (int it = 0; it < 2; ++it) {
        int wdx = it * 256 + tid;
        int pp = wdx >> 4, ci = wdx & 15;      // pos, chunk index
        int cl = ci * 8;
        int co = (pp + 5 * ci) & 31;           // stored column for rows 8ci..8ci+7
        float v[8];
#pragma unroll
        for (int t = 0; t < 8; t++) v[t] = sW[cl + t][co];
        __half2 h[4];
#pragma unroll
        for (int t = 0; t < 4; t++) h[t] = __floats2half2_rn(v[2 * t], v[2 * t + 1]);
        int col = (cl < 32) ? (c0 + cl) : (256 + 3 * c0 + (cl - 32));
        int m = p0 + pp;
        int kt = col >> 6, c6 = col & 63;
        char* base = reinterpret_cast<char*>(g_fused) + ((size_t)(b * 16 + kt) * 4096) * 128;
        const uint32_t* hw = reinterpret_cast<const uint32_t*>(h);
        uint4 pack;
        pack.x = hw[0];
        pack.y = hw[1];
        pack.z = hw[2];
        pack.w = hw[3];
        *reinterpret_cast<uint4*>(base + tile_off(m, c6 * 2)) = pack;
    }
}

// ----------------------------------------------------------------------------
// K2: blocks 0..7 = per-batch MLP gate (fp16) + g_sum re-zero;
//     block 8 = folded BN params
// ----------------------------------------------------------------------------
__global__ __launch_bounds__(256) void k_mlp(const float* __restrict__ w1, const float* __restrict__ w2,
                                             const float* __restrict__ gamma, const float* __restrict__ beta,
                                             const float* __restrict__ mean, const float* __restrict__ var) {
    int tid = threadIdx.x;
    int bx = blockIdx.x;
    if (bx == 8) {
        for (int o = tid; o < 512; o += 256) {
            float s = gamma[o] * rsqrtf(var[o] + 1e-5f);
            g_bns[o] = s;
            g_bnb[o] = beta[o] - mean[o] * s;
        }
        return;
    }
    int b = bx;
    __shared__ float s_mean[768];
    __shared__ float s_y1[48];
    for (int c = tid; c < 768; c += 256) s_mean[c] = g_sum[b * 768 + c] * (1.0f / 4096.0f);
    __syncthreads();
    int w = tid >> 5, lane = tid & 31;
#pragma unroll 1
    for (int i = 0; i < 6; i++) {
        int m = w + 8 * i;
        float acc = 0.f;
        for (int j = 0; j < 24; j++) {
            int c = lane + 32 * j;
            acc += s_mean[c] * w1[m * 768 + c];
        }
#pragma unroll
        for (int off = 16; off; off >>= 1) acc += __shfl_down_sync(0xffffffffu, acc, off);
        if (lane == 0) s_y1[m] = fmaxf(acc, 0.f);
    }
    __syncthreads();
    g_scale_h[b * 1024 + tid] = __float2half(1.0f);   // LL channels unscaled
    for (int c = tid; c < 768; c += 256) {
        float acc = 0.f;
#pragma unroll
        for (int m = 0; m < 48; m++) acc += s_y1[m] * w2[c * 48 + m];
        g_scale_h[b * 1024 + 256 + c] = __float2half_rn(1.0f / (1.0f + expf(-acc)));
    }
    // g_sum consumed above; zero this batch's slice for the next call
    for (int i = tid; i < 768; i += 256) g_sum[b * 768 + i] = 0.f;
}

// ----------------------------------------------------------------------------
// K4: PERSISTENT fp16 mma.sync GEMM. 304 CTAs (2/SM), each processes 3-4
//     tiles of 1024 with ONE continuous 3-slot bulk-copy pipeline (stage
//     counter st; slot=st%3, parity=(st/3)&1 — tile-agnostic). Next tile's
//     stages prefetch during the current tile's epilogue. Gate folded into
//     double-buffered B fragments (always applied; LL gate == 1.0 exact).
//     Direct-STG epilogue (no smem): each warp wavefront = 4 full 32B sectors.
//     8 warps (2m x 4n, 64x32 warp tiles). grid 304 x 256 threads.
// ----------------------------------------------------------------------------
static constexpr int A_BYTES = 128 * 64 * 2;          // 16 KB
static constexpr int B_BYTES = 128 * 64 * 2;          // 16 KB
static constexpr int STAGE   = A_BYTES + B_BYTES;     // 32 KB
static constexpr int SC_OFF  = 64;                    // gate scales (2 KB) after mbars
static constexpr int SM_OFF  = 4096;                  // stage buffers
static constexpr int SMEM_SZ = SM_OFF + 3 * STAGE;    // 102400
static constexpr int NCTA    = 304;                   // 2 per SM x 152 SMs
static constexpr int NTILES  = 1024;                  // 8 b x 32 mtile x 4 ntile

DI float silu(float z) { return z / (1.0f + __expf(-z)); }

__global__ __launch_bounds__(256, 2) void k_gemm(float* __restrict__ out) {
    extern __shared__ __align__(1024) char smem[];
    const uint32_t sb = smem_u32(smem);
    const int tid = threadIdx.x, lane = tid & 31, wid = tid >> 5;
    const int wm = wid & 1, wn = wid >> 1;            // warp grid 2(m) x 4(n)
    const int rq = lane >> 2, qq = lane & 3;
    const int bid = blockIdx.x;

    if (tid == 0) {
#pragma unroll
        for (int s = 0; s < 3; s++) {
            mbar_init(sb + 8 * s, 1);        // full[s]
            mbar_init(sb + 32 + 8 * s, 8);   // empty[s]: one arrive per warp
        }
    }
    asm volatile("fence.proxy.async.shared::cta;" ::: "memory");

    const int ntiles = (NTILES - bid + NCTA - 1) / NCTA;
    const int total  = ntiles * 16;

    int tile = bid;
    int b  = tile >> 7;
    int m0 = ((tile >> 2) & 31) * 128;
    int n0 = (tile & 3) * 128;

    // load gate scales for the first tile's batch: 1024 half = 512 u32
    {
        const uint32_t* src = reinterpret_cast<const uint32_t*>(g_scale_h + b * 1024);
        uint32_t* dst = reinterpret_cast<uint32_t*>(smem + SC_OFF);
        dst[tid] = src[tid];
        dst[tid + 256] = src[tid + 256];
    }
    __syncthreads();

    auto issue = [&](int stg) {   // load stage stg into slot stg%3 (tid 0 only)
        int tg = bid + (stg >> 4) * NCTA;
        int kt = stg & 15;
        int bb = tg >> 7;
        int mm = ((tg >> 2) & 31) * 128;
        int nn = (tg & 3) * 128;
        int s = stg % 3;
        mbar_expect_tx(sb + 8 * s, STAGE);
        const char* srcA = reinterpret_cast<const char*>(g_fused) +
                           ((size_t)(bb * 16 + kt) * 4096 + mm) * 128;
        const char* srcB = reinterpret_cast<const char*>(g_wh) +
                           ((size_t)kt * 512 + nn) * 128;
        bulk_g2s(sb + SM_OFF + s * STAGE, srcA, A_BYTES, sb + 8 * s);
        bulk_g2s(sb + SM_OFF + s * STAGE + A_BYTES, srcB, B_BYTES, sb + 8 * s);
    };
    if (tid == 0) { issue(0); issue(1); issue(2); }

    float acc[4][4][4];
#pragma unroll
    for (int i = 0; i < 4; i++)
#pragma unroll
        for (int j = 0; j < 4; j++)
#pragma unroll
            for (int r = 0; r < 4; r++) acc[i][j][r] = 0.f;

    // ldmatrix lane addressing (SW128-aware), constant per thread:
    const int x7  = lane & 7;
    const int khA = lane >> 4;                                 // k-half for A
    const int khB = (lane >> 3) & 1;                           // k-half for B
    const uint32_t rowA_off = (uint32_t)(wm * 64 + (lane & 15)) << 7;
    const uint32_t rowB_off = (uint32_t)(wn * 32 + (lane & 7) + ((lane >> 4) << 3)) << 7;
    const char* scp = smem + SC_OFF + qq * 4;                  // per-thread scale base

#pragma unroll 1
    for (int st = 0; st < total; ++st) {
        const int s = st % 3;
        const int kt = st & 15;
        mbar_wait(sb + 8 * s, (st / 3) & 1);              // full[s]

        const uint32_t baseA = sb + SM_OFF + s * STAGE + rowA_off;
        const uint32_t baseB = sb + SM_OFF + s * STAGE + A_BYTES + rowB_off;
        const char* sck = scp + kt * 128;

        // double-buffered, gate-scaled B fragments (gate == 1.0 for LL, exact)
        uint32_t bf0[4][2], bf1[4][2];
        auto loadB = [&](int ks, uint32_t (&bf)[4][2]) {
            const uint32_t cB = (uint32_t)(((2 * ks + khB) ^ x7) << 4);
            ldsm4(bf[0][0], bf[0][1], bf[1][0], bf[1][1], baseB + cB);
            ldsm4(bf[2][0], bf[2][1], bf[3][0], bf[3][1], baseB + (1 << 11) + cB);
            // gate: k = kt*64 + ks*16 + g*8 + 2qq + {0,1}; reg g selects +16B
            uint32_t s0 = *reinterpret_cast<const uint32_t*>(sck + ks * 32);
            uint32_t s1 = *reinterpret_cast<const uint32_t*>(sck + ks * 32 + 16);
#pragma unroll
            for (int j = 0; j < 4; j++) {
                bf[j][0] = h2mul(bf[j][0], s0);
                bf[j][1] = h2mul(bf[j][1], s1);
            }
        };
        loadB(0, bf0);

#pragma unroll
        for (int ks = 0; ks < 4; ++ks) {
            const uint32_t cA = (uint32_t)(((2 * ks + khA) ^ x7) << 4);
            uint32_t a[4][4];
#pragma unroll
            for (int i = 0; i < 4; i++)
                ldsm4(a[i][0], a[i][1], a[i][2], a[i][3], baseA + (i << 11) + cA);
            if (ks < 3) loadB(ks + 1, (ks & 1) ? bf0 : bf1);
            uint32_t (&cur)[4][2] = (ks & 1) ? bf1 : bf0;
#pragma unroll
            for (int i = 0; i < 4; i++)
#pragma unroll
                for (int j = 0; j < 4; j++) mma16(acc[i][j], a[i], cur[j]);
        }

        if (lane == 0) mbar_arrive(sb + 32 + 8 * s);      // warp done with slot s
        if (tid == 0 && st + 3 < total) {
            mbar_wait(sb + 32 + 8 * s, (st / 3) & 1);     // all warps consumed slot s
            issue(st + 3);                                 // may belong to next tile
        }

        if (kt == 15) {
            __syncthreads();    // all warps done with this tile's mainloop & scales

            // ---- direct-STG epilogue: BN + SiLU from fragments (no smem) ----
#pragma unroll
            for (int j = 0; j < 4; j++) {
                int n = n0 + wn * 32 + j * 8 + 2 * qq;
                float sA = g_bns[n],     tA = g_bnb[n];
                float sB = g_bns[n + 1], tB = g_bnb[n + 1];
                float* p = out + (((size_t)(b * 512 + n)) << 12) + m0 + wm * 64 + rq;
#pragma unroll
                for (int i = 0; i < 4; i++) {
                    float* q = p + i * 16;
                    q[0]    = silu(acc[i][j][0] * sA + tA);
                    q[8]    = silu(acc[i][j][2] * sA + tA);
                    q[4096] = silu(acc[i][j][1] * sB + tB);
                    q[4104] = silu(acc[i][j][3] * sB + tB);
                    acc[i][j][0] = acc[i][j][1] = acc[i][j][2] = acc[i][j][3] = 0.f;
                }
            }

            // advance to next tile; load its gate scales
            tile += NCTA;
            if (tile < NTILES) {
                b  = tile >> 7;
                m0 = ((tile >> 2) & 31) * 128;
                n0 = (tile & 3) * 128;
                const uint32_t* src = reinterpret_cast<const uint32_t*>(g_scale_h + b * 1024);
                uint32_t* dst = reinterpret_cast<uint32_t*>(smem + SC_OFF);
                dst[tid] = src[tid];
                dst[tid + 256] = src[tid + 256];
            }
            __syncthreads();    // scale writes visible before next mainloop
        }
    }
}

// ----------------------------------------------------------------------------
// Launch (3 kernels per call; g_sum starts zeroed: zero-init + k_mlp tail)
// ----------------------------------------------------------------------------
extern "C" void kernel_launch(void* const* d_in, const int* in_sizes, int n_in,
                              void* d_out, int out_size) {
    const float* x      = (const float*)d_in[0];
    const float* w1     = (const float*)d_in[1];
    const float* w2     = (const float*)d_in[2];
    const float* conv_w = (const float*)d_in[3];
    const float* gamma  = (const float*)d_in[4];
    const float* beta   = (const float*)d_in[5];
    const float* mean   = (const float*)d_in[6];
    const float* var    = (const float*)d_in[7];
    float* out = (float*)d_out;
    (void)in_sizes; (void)n_in; (void)out_size;

    cudaFuncSetAttribute(k_gemm, cudaFuncAttributeMaxDynamicSharedMemorySize, SMEM_SZ);

    k_wavelet<<<dim3(128, 8, 9), 256>>>(x, conv_w);
    k_mlp<<<9, 256>>>(w1, w2, gamma, beta, mean, var);
    k_gemm<<<NCTA, 256, SMEM_SZ>>>(out);
}

// round 17
// speedup vs baseline: 1.0967x; 1.0247x over previous
#include <cuda_runtime.h>
#include <cuda_fp16.h>
#include <cstdint>
#include <math.h>

#define DI __device__ __forceinline__

// ----------------------------------------------------------------------------
// Device scratch (no cudaMalloc allowed). K-major tiled, SW128-preswizzled:
//   g_fused: [b][kt=16][m=4096][64ch]  (128B rows, swizzled within 1KB blocks)
//   g_wh   : [kt=16][o=512][64ch]      (shared fp16 weights, unscaled)
// ----------------------------------------------------------------------------
__device__ __half g_fused[8ull * 16ull * 4096ull * 64ull];
__device__ __half g_wh   [16ull * 512ull * 64ull];
__device__ __half g_scale_h[8 * 1024];               // per-(b,ch) gate fp16 (1.0 for LL)
__device__ float  g_sum  [8 * 768];                  // hf channel sums (zero-init; re-zeroed each call)
__device__ float  g_bns  [512];                      // folded BN scale
__device__ float  g_bnb  [512];                      // folded BN bias

// ----------------------------------------------------------------------------
// Helpers (baseline PTX only — no tcgen05 / no 'a'-gated features)
// ----------------------------------------------------------------------------
DI uint32_t sw128(uint32_t o) { return o ^ ((o >> 3) & 0x70u); }

DI uint32_t smem_u32(const void* p) {
    uint32_t a;
    asm("{ .reg .u64 t; cvta.to.shared.u64 t, %1; cvt.u32.u64 %0, t; }" : "=r"(a) : "l"(p));
    return a;
}
// global byte offset for (row, col2B) in a preswizzled [rows][64ch] tile
DI uint32_t tile_off(uint32_t row, uint32_t colbyte) {
    uint32_t off = row * 128u + colbyte;
    return (off & ~1023u) + sw128(off & 1023u);
}

DI void mbar_init(uint32_t mbar, uint32_t cnt) {
    asm volatile("mbarrier.init.shared.b64 [%0], %1;" :: "r"(mbar), "r"(cnt) : "memory");
}
DI void mbar_expect_tx(uint32_t mbar, uint32_t bytes) {
    asm volatile("mbarrier.arrive.expect_tx.shared.b64 _, [%0], %1;"
                 :: "r"(mbar), "r"(bytes) : "memory");
}
DI void mbar_arrive(uint32_t mbar) {
    asm volatile("mbarrier.arrive.shared.b64 _, [%0];" :: "r"(mbar) : "memory");
}
DI void mbar_wait(uint32_t mbar, uint32_t parity) {
    asm volatile(
        "{\n\t.reg .pred P1;\n\t"
        "LAB_WAIT_%=:\n\t"
        "mbarrier.try_wait.parity.acquire.cta.shared::cta.b64 P1, [%0], %1, 0x989680;\n\t"
        "@P1 bra.uni LAB_DONE_%=;\n\t"
        "bra.uni LAB_WAIT_%=;\n\t"
        "LAB_DONE_%=:\n\t}"
        :: "r"(mbar), "r"(parity) : "memory");
}
// 1-D bulk async copy global -> shared (sm_90 baseline; single thread issues)
DI void bulk_g2s(uint32_t dst, const void* src, uint32_t bytes, uint32_t mbar) {
    asm volatile(
        "cp.async.bulk.shared::cluster.global.mbarrier::complete_tx::bytes [%0], [%1], %2, [%3];"
        :: "r"(dst), "l"(__cvta_generic_to_global(src)), "r"(bytes), "r"(mbar) : "memory");
}

// ldmatrix x4: four 8x8 b16 matrices, lane-supplied row addresses
DI void ldsm4(uint32_t& r0, uint32_t& r1, uint32_t& r2, uint32_t& r3, uint32_t addr) {
    asm volatile("ldmatrix.sync.aligned.m8n8.x4.shared.b16 {%0,%1,%2,%3}, [%4];"
                 : "=r"(r0), "=r"(r1), "=r"(r2), "=r"(r3) : "r"(addr));
}

// fp16 HMMA with fp32 accumulate: D[16x8] += A[16x16] * B[16x8]
DI void mma16(float* c, const uint32_t* a, const uint32_t* b) {
    asm volatile(
        "mma.sync.aligned.m16n8k16.row.col.f32.f16.f16.f32 "
        "{%0,%1,%2,%3}, {%4,%5,%6,%7}, {%8,%9}, {%0,%1,%2,%3};"
        : "+f"(c[0]), "+f"(c[1]), "+f"(c[2]), "+f"(c[3])
        : "r"(a[0]), "r"(a[1]), "r"(a[2]), "r"(a[3]), "r"(b[0]), "r"(b[1]));
}

DI uint32_t h2mul(uint32_t a, uint32_t s) {
    uint32_t d;
    asm("mul.rn.f16x2 %0, %1, %2;" : "=r"(d) : "r"(a), "r"(s));
    return d;
}

// ----------------------------------------------------------------------------
// K1: Haar DWT -> preswizzled K-major g_fused + hf channel sums.
//     blockIdx.z==8 blocks instead convert conv_w -> preswizzled fp16 g_wh.
// grid (128 pos-tiles, 8 c-tiles, 9), 256 threads
// smem layout: sW[128][33]; element (r, pp) at column (pp + 5*(r>>3)) & 31.
//   rows 0..31 = LL channel cc; rows 32..127 = hf, r = 32 + 3*cc + subband.
// Phase 1 is float4-vectorized: h2 is constant per block (p0 multiple of 32),
// each thread loads 2x float4 covering two adjacent output positions; warp
// covers 2 channels via half-warps, 2 iterations.
// ----------------------------------------------------------------------------
__global__ __launch_bounds__(256) void k_wavelet(const float* __restrict__ x,
                                                 const float* __restrict__ conv_w) {
    const int tid = threadIdx.x;
    if (blockIdx.z == 8) {      // weight conversion: 262144 half2 over 1024 blocks
        int u  = (blockIdx.y * 128 + blockIdx.x) * 256 + tid;
        int kt = u >> 14;                       // 16384 half2 per kt tile (512 rows x 32)
        int r2 = u & 16383;
        int o  = r2 >> 5;
        int c2 = r2 & 31;
        int c  = kt * 64 + 2 * c2;
        __half2 v = __floats2half2_rn(conv_w[o * 1024 + c], conv_w[o * 1024 + c + 1]);
        char* base = reinterpret_cast<char*>(g_wh) + (size_t)kt * 512 * 128;
        *reinterpret_cast<__half2*>(base + tile_off(o, c2 * 4)) = v;
        return;
    }

    const int b = blockIdx.z, c0 = blockIdx.y * 32, p0 = blockIdx.x * 32;
    const int lane = tid & 31, w = tid >> 5;
    const int h2 = p0 >> 6, w0 = p0 & 63;      // constant image row-pair per block

    __shared__ float sW[128][33];

#pragma unroll
    for (int it = 0; it < 2; ++it) {
        const int h = lane >> 4, t = lane & 15;
        const int cc = it * 16 + w * 2 + h;
        const float* xr = x + (((size_t)(b * 256 + c0 + cc) * 128 + 2 * h2) * 128
                               + 2 * w0 + 4 * t);
        float4 r0 = *reinterpret_cast<const float4*>(xr);
        float4 r1 = *reinterpret_cast<const float4*>(xr + 128);

        const int rh = 32 + 3 * cc;
        const int sLLc = 5 * (cc >> 3);
        const int s0 = 5 * (rh >> 3), s1 = 5 * ((rh + 1) >> 3), s2 = 5 * ((rh + 2) >> 3);
        const int pA = 2 * t, pB = 2 * t + 1;

        // pos pA from (r0.x, r0.y, r1.x, r1.y); pos pB from (r0.z, r0.w, r1.z, r1.w)
        sW[cc][(pA + sLLc) & 31]     = 0.5f * (r0.x + r0.y + r1.x + r1.y);
        sW[cc][(pB + sLLc) & 31]     = 0.5f * (r0.z + r0.w + r1.z + r1.w);
        sW[rh][(pA + s0) & 31]       = 0.5f * (r0.x + r0.y - r1.x - r1.y);
        sW[rh][(pB + s0) & 31]       = 0.5f * (r0.z + r0.w - r1.z - r1.w);
        sW[rh + 1][(pA + s1) & 31]   = 0.5f * (r0.x - r0.y + r1.x - r1.y);
        sW[rh + 1][(pB + s1) & 31]   = 0.5f * (r0.z - r0.w + r1.z - r1.w);
        sW[rh + 2][(pA + s2) & 31]   = 0.5f * (r0.x - r0.y - r1.x + r1.y);
        sW[rh + 2][(pB + s2) & 31]   = 0.5f * (r0.z - r0.w - r1.z + r1.w);
    }
    __syncthreads();

    // hf channel sums: rows 32..127 = channel 3*c0 + rr, reduced by 4-thread groups
    {
        int q = tid & 3;
        {
            int rr = tid >> 2;                 // rr 0..63 -> rows 32..95
            int row = 32 + rr;
            int sh = 5 * (row >> 3);
            float v = 0.f;
#pragma unroll
            for (int t = 0; t < 8; t++) v += sW[row][(q * 8 + t + sh) & 31];
            v += __shfl_down_sync(0xffffffffu, v, 1);
            v += __shfl_down_sync(0xffffffffu, v, 2);
            if (q == 0) atomicAdd(&g_sum[b * 768 + 3 * c0 + rr], v);
        }
        if (tid < 128) {
            int rr = 64 + (tid >> 2);          // rows 96..127
            int row = 32 + rr;
            int sh = 5 * (row >> 3);
            float v = 0.f;
#pragma unroll
            for (int t = 0; t < 8; t++) v += sW[row][(q * 8 + t + sh) & 31];
            v += __shfl_down_sync(0xffffffffu, v, 1);
            v += __shfl_down_sync(0xffffffffu, v, 2);
            if (q == 0) atomicAdd(&g_sum[b * 768 + 3 * c0 + rr], v);
        }
    }

    // Write as 16B chunks (8 consecutive output channels); rows uniform per chunk.
#pragma unroll
    for (int it = 0; it < 2; ++it) {
        int wdx = it * 256 + tid;
        int pp = wdx >> 4, ci = wdx & 15;      // pos, chunk index
        int cl = ci * 8;
        int co = (pp + 5 * ci) & 31;           // stored column for rows 8ci..8ci+7
        float v[8];
#pragma unroll
        for (int t = 0; t < 8; t++) v[t] = sW[cl + t][co];
        __half2 h[4];
#pragma unroll
        for (int t = 0; t < 4; t++) h[t] = __floats2half2_rn(v[2 * t], v[2 * t + 1]);
        int col = (cl < 32) ? (c0 + cl) : (256 + 3 * c0 + (cl - 32));
        int m = p0 + pp;
        int kt = col >> 6, c6 = col & 63;
        char* base = reinterpret_cast<char*>(g_fused) + ((size_t)(b * 16 + kt) * 4096) * 128;
        const uint32_t* hw = reinterpret_cast<const uint32_t*>(h);
        uint4 pack;
        pack.x = hw[0];
        pack.y = hw[1];
        pack.z = hw[2];
        pack.w = hw[3];
        *reinterpret_cast<uint4*>(base + tile_off(m, c6 * 2)) = pack;
    }
}

// ----------------------------------------------------------------------------
// K2: blocks 0..7 = per-batch MLP gate (fp16) + g_sum re-zero;
//     block 8 = folded BN params
// ----------------------------------------------------------------------------
__global__ __launch_bounds__(256) void k_mlp(const float* __restrict__ w1, const float* __restrict__ w2,
                                             const float* __restrict__ gamma, const float* __restrict__ beta,
                                             const float* __restrict__ mean, const float* __restrict__ var) {
    int tid = threadIdx.x;
    int bx = blockIdx.x;
    if (bx == 8) {
        for (int o = tid; o < 512; o += 256) {
            float s = gamma[o] * rsqrtf(var[o] + 1e-5f);
            g_bns[o] = s;
            g_bnb[o] = beta[o] - mean[o] * s;
        }
        return;
    }
    int b = bx;
    __shared__ float s_mean[768];
    __shared__ float s_y1[48];
    for (int c = tid; c < 768; c += 256) s_mean[c] = g_sum[b * 768 + c] * (1.0f / 4096.0f);
    __syncthreads();
    int w = tid >> 5, lane = tid & 31;
#pragma unroll 1
    for (int i = 0; i < 6; i++) {
        int m = w + 8 * i;
        float acc = 0.f;
        for (int j = 0; j < 24; j++) {
            int c = lane + 32 * j;
            acc += s_mean[c] * w1[m * 768 + c];
        }
#pragma unroll
        for (int off = 16; off; off >>= 1) acc += __shfl_down_sync(0xffffffffu, acc, off);
        if (lane == 0) s_y1[m] = fmaxf(acc, 0.f);
    }
    __syncthreads();
    g_scale_h[b * 1024 + tid] = __float2half(1.0f);   // LL channels unscaled
    for (int c = tid; c < 768; c += 256) {
        float acc = 0.f;
#pragma unroll
        for (int m = 0; m < 48; m++) acc += s_y1[m] * w2[c * 48 + m];
        g_scale_h[b * 1024 + 256 + c] = __float2half_rn(1.0f / (1.0f + expf(-acc)));
    }
    // g_sum consumed above; zero this batch's slice for the next call
    for (int i = tid; i < 768; i += 256) g_sum[b * 768 + i] = 0.f;
}

// ----------------------------------------------------------------------------
// K4: PERSISTENT fp16 mma.sync GEMM. 304 CTAs (2/SM), each processes 3-4
//     tiles of 1024 with ONE continuous 3-slot bulk-copy pipeline (stage
//     counter st; slot=st%3, parity=(st/3)&1 — tile-agnostic). Next tile's
//     stages prefetch during the current tile's epilogue. Gate folded into
//     double-buffered B fragments (always applied; LL gate == 1.0 exact).
//     Direct-STG epilogue (no smem): each warp wavefront = 4 full 32B sectors.
//     8 warps (2m x 4n, 64x32 warp tiles). grid 304 x 256 threads.
// ----------------------------------------------------------------------------
static constexpr int A_BYTES = 128 * 64 * 2;          // 16 KB
static constexpr int B_BYTES = 128 * 64 * 2;          // 16 KB
static constexpr int STAGE   = A_BYTES + B_BYTES;     // 32 KB
static constexpr int SC_OFF  = 64;                    // gate scales (2 KB) after mbars
static constexpr int SM_OFF  = 4096;                  // stage buffers
static constexpr int SMEM_SZ = SM_OFF + 3 * STAGE;    // 102400
static constexpr int NCTA    = 304;                   // 2 per SM x 152 SMs
static constexpr int NTILES  = 1024;                  // 8 b x 32 mtile x 4 ntile

DI float silu(float z) { return z / (1.0f + __expf(-z)); }

__global__ __launch_bounds__(256, 2) void k_gemm(float* __restrict__ out) {
    extern __shared__ __align__(1024) char smem[];
    const uint32_t sb = smem_u32(smem);
    const int tid = threadIdx.x, lane = tid & 31, wid = tid >> 5;
    const int wm = wid & 1, wn = wid >> 1;            // warp grid 2(m) x 4(n)
    const int rq = lane >> 2, qq = lane & 3;
    const int bid = blockIdx.x;

    if (tid == 0) {
#pragma unroll
        for (int s = 0; s < 3; s++) {
            mbar_init(sb + 8 * s, 1);        // full[s]
            mbar_init(sb + 32 + 8 * s, 8);   // empty[s]: one arrive per warp
        }
    }
    asm volatile("fence.proxy.async.shared::cta;" ::: "memory");

    const int ntiles = (NTILES - bid + NCTA - 1) / NCTA;
    const int total  = ntiles * 16;

    int tile = bid;
    int b  = tile >> 7;
    int m0 = ((tile >> 2) & 31) * 128;
    int n0 = (tile & 3) * 128;

    // load gate scales for the first tile's batch: 1024 half = 512 u32
    {
        const uint32_t* src = reinterpret_cast<const uint32_t*>(g_scale_h + b * 1024);
        uint32_t* dst = reinterpret_cast<uint32_t*>(smem + SC_OFF);
        dst[tid] = src[tid];
        dst[tid + 256] = src[tid + 256];
    }
    __syncthreads();

    auto issue = [&](int stg) {   // load stage stg into slot stg%3 (tid 0 only)
        int tg = bid + (stg >> 4) * NCTA;
        int kt = stg & 15;
        int bb = tg >> 7;
        int mm = ((tg >> 2) & 31) * 128;
        int nn = (tg & 3) * 128;
        int s = stg % 3;
        mbar_expect_tx(sb + 8 * s, STAGE);
        const char* srcA = reinterpret_cast<const char*>(g_fused) +
                           ((size_t)(bb * 16 + kt) * 4096 + mm) * 128;
        const char* srcB = reinterpret_cast<const char*>(g_wh) +
                           ((size_t)kt * 512 + nn) * 128;
        bulk_g2s(sb + SM_OFF + s * STAGE, srcA, A_BYTES, sb + 8 * s);
        bulk_g2s(sb + SM_OFF + s * STAGE + A_BYTES, srcB, B_BYTES, sb + 8 * s);
    };
    if (tid == 0) { issue(0); issue(1); issue(2); }

    float acc[4][4][4];
#pragma unroll
    for (int i = 0; i < 4; i++)
#pragma unroll
        for (int j = 0; j < 4; j++)
#pragma unroll
            for (int r = 0; r < 4; r++) acc[i][j][r] = 0.f;

    // ldmatrix lane addressing (SW128-aware), constant per thread:
    const int x7  = lane & 7;
    const int khA = lane >> 4;                                 // k-half for A
    const int khB = (lane >> 3) & 1;                           // k-half for B
    const uint32_t rowA_off = (uint32_t)(wm * 64 + (lane & 15)) << 7;
    const uint32_t rowB_off = (uint32_t)(wn * 32 + (lane & 7) + ((lane >> 4) << 3)) << 7;
    const char* scp = smem + SC_OFF + qq * 4;                  // per-thread scale base

#pragma unroll 1
    for (int st = 0; st < total; ++st) {
        const int s = st % 3;
        const int kt = st & 15;
        mbar_wait(sb + 8 * s, (st / 3) & 1);              // full[s]

        const uint32_t baseA = sb + SM_OFF + s * STAGE + rowA_off;
        const uint32_t baseB = sb + SM_OFF + s * STAGE + A_BYTES + rowB_off;
        const char* sck = scp + kt * 128;

        // double-buffered, gate-scaled B fragments (gate == 1.0 for LL, exact)
        uint32_t bf0[4][2], bf1[4][2];
        auto loadB = [&](int ks, uint32_t (&bf)[4][2]) {
            const uint32_t cB = (uint32_t)(((2 * ks + khB) ^ x7) << 4);
            ldsm4(bf[0][0], bf[0][1], bf[1][0], bf[1][1], baseB + cB);
            ldsm4(bf[2][0], bf[2][1], bf[3][0], bf[3][1], baseB + (1 << 11) + cB);
            // gate: k = kt*64 + ks*16 + g*8 + 2qq + {0,1}; reg g selects +16B
            uint32_t s0 = *reinterpret_cast<const uint32_t*>(sck + ks * 32);
            uint32_t s1 = *reinterpret_cast<const uint32_t*>(sck + ks * 32 + 16);
#pragma unroll
            for (int j = 0; j < 4; j++) {
                bf[j][0] = h2mul(bf[j][0], s0);
                bf[j][1] = h2mul(bf[j][1], s1);
            }
        };
        loadB(0, bf0);

#pragma unroll
        for (int ks = 0; ks < 4; ++ks) {
            const uint32_t cA = (uint32_t)(((2 * ks + khA) ^ x7) << 4);
            uint32_t a[4][4];
#pragma unroll
            for (int i = 0; i < 4; i++)
                ldsm4(a[i][0], a[i][1], a[i][2], a[i][3], baseA + (i << 11) + cA);
            if (ks < 3) loadB(ks + 1, (ks & 1) ? bf0 : bf1);
            uint32_t (&cur)[4][2] = (ks & 1) ? bf1 : bf0;
#pragma unroll
            for (int i = 0; i < 4; i++)
#pragma unroll
                for (int j = 0; j < 4; j++) mma16(acc[i][j], a[i], cur[j]);
        }

        if (lane == 0) mbar_arrive(sb + 32 + 8 * s);      // warp done with slot s
        if (tid == 0 && st + 3 < total) {
            mbar_wait(sb + 32 + 8 * s, (st / 3) & 1);     // all warps consumed slot s
            issue(st + 3);                                 // may belong to next tile
        }

        if (kt == 15) {
            __syncthreads();    // all warps done with this tile's mainloop & scales

            // ---- direct-STG epilogue: BN + SiLU from fragments (no smem) ----
#pragma unroll
            for (int j = 0; j < 4; j++) {
                int n = n0 + wn * 32 + j * 8 + 2 * qq;
                float sA = g_bns[n],     tA = g_bnb[n];
                float sB = g_bns[n + 1], tB = g_bnb[n + 1];
                float* p = out + (((size_t)(b * 512 + n)) << 12) + m0 + wm * 64 + rq;
#pragma unroll
                for (int i = 0; i < 4; i++) {
                    float* q = p + i * 16;
                    q[0]    = silu(acc[i][j][0] * sA + tA);
                    q[8]    = silu(acc[i][j][2] * sA + tA);
                    q[4096] = silu(acc[i][j][1] * sB + tB);
                    q[4104] = silu(acc[i][j][3] * sB + tB);
                    acc[i][j][0] = acc[i][j][1] = acc[i][j][2] = acc[i][j][3] = 0.f;
                }
            }

            // advance to next tile; load its gate scales
            tile += NCTA;
            if (tile < NTILES) {
                b  = tile >> 7;
                m0 = ((tile >> 2) & 31) * 128;
                n0 = (tile & 3) * 128;
                const uint32_t* src = reinterpret_cast<const uint32_t*>(g_scale_h + b * 1024);
                uint32_t* dst = reinterpret_cast<uint32_t*>(smem + SC_OFF);
                dst[tid] = src[tid];
                dst[tid + 256] = src[tid + 256];
            }
            __syncthreads();    // scale writes visible before next mainloop
        }
    }
}

// ----------------------------------------------------------------------------
// Launch (3 kernels per call; g_sum starts zeroed: zero-init + k_mlp tail)
// ----------------------------------------------------------------------------
extern "C" void kernel_launch(void* const* d_in, const int* in_sizes, int n_in,
                              void* d_out, int out_size) {
    const float* x      = (const float*)d_in[0];
    const float* w1     = (const float*)d_in[1];
    const float* w2     = (const float*)d_in[2];
    const float* conv_w = (const float*)d_in[3];
    const float* gamma  = (const float*)d_in[4];
    const float* beta   = (const float*)d_in[5];
    const float* mean   = (const float*)d_in[6];
    const float* var    = (const float*)d_in[7];
    float* out = (float*)d_out;
    (void)in_sizes; (void)n_in; (void)out_size;

    cudaFuncSetAttribute(k_gemm, cudaFuncAttributeMaxDynamicSharedMemorySize, SMEM_SZ);

    k_wavelet<<<dim3(128, 8, 9), 256>>>(x, conv_w);
    k_mlp<<<9, 256>>>(w1, w2, gamma, beta, mean, var);
    k_gemm<<<NCTA, 256, SMEM_SZ>>>(out);
}